// round 2
// baseline (speedup 1.0000x reference)
#include <cuda_runtime.h>
#include <math.h>

#define N_NODES 50000
#define N_EDGES 600000
#define N_GRAPHS 1024
#define FEAT 128

// ---------------- scratch (static device globals; no allocation) ----------------
__device__ float d_bufA[N_NODES * FEAT];   // layer input / aggregated output
__device__ float d_bufB[N_NODES * FEAT];   // g = (X@W) * dinv
__device__ float d_dinv[N_NODES];
__device__ int   d_cnt[N_NODES];           // in-degree (dst counts)
__device__ int   d_fill[N_NODES];
__device__ int   d_rowptr[N_NODES + 1];
__device__ int   d_srcE[N_EDGES];
__device__ int   d_dstE[N_EDGES];
__device__ int   d_col[N_EDGES];           // CSR col (src) sorted by dst
__device__ int   d_gcnt[N_GRAPHS];
__device__ int   d_gptr[N_GRAPHS + 1];
__device__ float d_pool[N_GRAPHS * 256];
__device__ float d_m1[N_GRAPHS * 128];
__device__ float d_m2[N_GRAPHS * 128];
__device__ int   d_mode;                   // 1 = indices are int64, 0 = int32

// ---------------- dtype detection ----------------
// If edge_index was delivered as int64, every odd 32-bit word is a zero high
// word (values are < 2^31). If int32, odd words are random src indices —
// the chance that 32 of them are all zero is ~(1/50000)^32.
__global__ void k_detect(const int* __restrict__ ei) {
    int z = 0;
    #pragma unroll
    for (int i = 1; i < 64; i += 2) z |= ei[i];
    d_mode = (z == 0) ? 1 : 0;
}

// ---------------- zero counters ----------------
__global__ void k_zero() {
    int i = blockIdx.x * blockDim.x + threadIdx.x;
    if (i < N_NODES) { d_cnt[i] = 0; d_fill[i] = 0; }
    if (i < N_GRAPHS) d_gcnt[i] = 0;
}

__device__ __forceinline__ int clampi(int v, int hi) {
    return v < 0 ? 0 : (v > hi ? hi : v);
}

// ---------------- edge prep: load (either dtype) + dst histogram ----------------
__global__ void k_prep(const int* __restrict__ ei) {
    int e = blockIdx.x * blockDim.x + threadIdx.x;
    if (e < N_EDGES) {
        int s, d;
        if (d_mode) {
            s = ei[2 * e];
            d = ei[2 * (N_EDGES + e)];
        } else {
            s = ei[e];
            d = ei[N_EDGES + e];
        }
        s = clampi(s, N_NODES - 1);
        d = clampi(d, N_NODES - 1);
        d_srcE[e] = s;
        d_dstE[e] = d;
        atomicAdd(&d_cnt[d], 1);
    }
}

// ---------------- generic single-block exclusive scan ----------------
// which==0: cnt[N_NODES] -> rowptr ; which==1: gcnt[N_GRAPHS] -> gptr
__global__ void k_scan(int which) {
    const int* in  = (which == 0) ? d_cnt : d_gcnt;
    int*       out = (which == 0) ? d_rowptr : d_gptr;
    int n = (which == 0) ? N_NODES : N_GRAPHS;

    __shared__ int warp_sums[32];
    __shared__ int carry;
    int tid = threadIdx.x;
    int lane = tid & 31, wid = tid >> 5;
    if (tid == 0) carry = 0;
    __syncthreads();

    for (int base = 0; base < n; base += blockDim.x) {
        int i = base + tid;
        int v = (i < n) ? in[i] : 0;
        int incl = v;
        #pragma unroll
        for (int o = 1; o < 32; o <<= 1) {
            int t = __shfl_up_sync(0xFFFFFFFFu, incl, o);
            if (lane >= o) incl += t;
        }
        if (lane == 31) warp_sums[wid] = incl;
        __syncthreads();
        if (wid == 0) {
            int ws = warp_sums[lane];
            #pragma unroll
            for (int o = 1; o < 32; o <<= 1) {
                int t = __shfl_up_sync(0xFFFFFFFFu, ws, o);
                if (lane >= o) ws += t;
            }
            warp_sums[lane] = ws;
        }
        __syncthreads();
        int warp_off = (wid == 0) ? 0 : warp_sums[wid - 1];
        int total = warp_sums[31];
        int excl = carry + warp_off + incl - v;
        if (i < n) out[i] = excl;
        __syncthreads();
        if (tid == 0) carry += total;
        __syncthreads();
    }
    if (tid == 0) out[n] = carry;
}

// ---------------- CSR scatter ----------------
__global__ void k_fill() {
    int e = blockIdx.x * blockDim.x + threadIdx.x;
    if (e < N_EDGES) {
        int d = d_dstE[e];
        int pos = d_rowptr[d] + atomicAdd(&d_fill[d], 1);
        d_col[pos] = d_srcE[e];
    }
}

__global__ void k_dinv() {
    int i = blockIdx.x * blockDim.x + threadIdx.x;
    if (i < N_NODES) d_dinv[i] = rsqrtf((float)d_cnt[i] + 1.0f);
}

__global__ void k_ghist(const int* __restrict__ batch) {
    int i = blockIdx.x * blockDim.x + threadIdx.x;
    if (i < N_NODES) {
        int g = d_mode ? batch[2 * i] : batch[i];
        atomicAdd(&d_gcnt[clampi(g, N_GRAPHS - 1)], 1);
    }
}

// ---------------- GEMM: G = (X @ W) * dinv[row]   (M x 128 @ 128 x 128) ---------
// block: 256 threads, tile BM=64 x BN=128, BK=32; thread tile 4x8
__global__ void k_gemm(const float* __restrict__ Xext, int useExt,
                       const float* __restrict__ W, int M) {
    const float* __restrict__ X = useExt ? Xext : d_bufA;
    __shared__ float  Xs[64][33];
    __shared__ float4 Ws4[32][32];

    int tid = threadIdx.x;
    int cg = tid & 15;   // col group: 8 cols each
    int rg = tid >> 4;   // row group: 4 rows each
    int row0 = blockIdx.x * 64;

    float acc[4][8];
    #pragma unroll
    for (int i = 0; i < 4; i++)
        #pragma unroll
        for (int j = 0; j < 8; j++) acc[i][j] = 0.f;

    for (int k0 = 0; k0 < 128; k0 += 32) {
        #pragma unroll
        for (int j = 0; j < 8; j++) {
            int e = tid + j * 256;
            int r = e >> 5, c = e & 31;
            int gr = row0 + r;
            Xs[r][c] = (gr < M) ? X[gr * 128 + k0 + c] : 0.f;
        }
        #pragma unroll
        for (int j = 0; j < 4; j++) {
            int e = tid + j * 256;
            int r = e >> 5, c = e & 31;
            Ws4[r][c] = ((const float4*)W)[(k0 + r) * 32 + c];
        }
        __syncthreads();
        #pragma unroll
        for (int k = 0; k < 32; k++) {
            float xv[4];
            #pragma unroll
            for (int i = 0; i < 4; i++) xv[i] = Xs[rg * 4 + i][k];
            float4 w0 = Ws4[k][cg * 2];
            float4 w1 = Ws4[k][cg * 2 + 1];
            float wv[8] = {w0.x, w0.y, w0.z, w0.w, w1.x, w1.y, w1.z, w1.w};
            #pragma unroll
            for (int i = 0; i < 4; i++)
                #pragma unroll
                for (int j = 0; j < 8; j++)
                    acc[i][j] = fmaf(xv[i], wv[j], acc[i][j]);
        }
        __syncthreads();
    }
    #pragma unroll
    for (int i = 0; i < 4; i++) {
        int r = row0 + rg * 4 + i;
        if (r < M) {
            float dv = d_dinv[r];
            float4 o0 = make_float4(acc[i][0] * dv, acc[i][1] * dv,
                                    acc[i][2] * dv, acc[i][3] * dv);
            float4 o1 = make_float4(acc[i][4] * dv, acc[i][5] * dv,
                                    acc[i][6] * dv, acc[i][7] * dv);
            ((float4*)d_bufB)[r * 32 + cg * 2]     = o0;
            ((float4*)d_bufB)[r * 32 + cg * 2 + 1] = o1;
        }
    }
}

// ---------------- aggregate: out = relu(dinv[i]*(G[i] + sum_nbr G[src]) + b) ----
// one warp per dst node; CSR gather, no atomics
__global__ void k_agg(const float* __restrict__ bias) {
    int warp = (blockIdx.x * blockDim.x + threadIdx.x) >> 5;
    int lane = threadIdx.x & 31;
    if (warp >= N_NODES) return;
    const float4* __restrict__ G4 = (const float4*)d_bufB;

    float4 acc = G4[warp * 32 + lane];   // self loop (g[i])
    int s = d_rowptr[warp], e = d_rowptr[warp + 1];
    int j = s;
    for (; j + 1 < e; j += 2) {
        int s0 = d_col[j], s1 = d_col[j + 1];
        float4 v0 = G4[s0 * 32 + lane];
        float4 v1 = G4[s1 * 32 + lane];
        acc.x += v0.x + v1.x; acc.y += v0.y + v1.y;
        acc.z += v0.z + v1.z; acc.w += v0.w + v1.w;
    }
    if (j < e) {
        float4 v0 = G4[d_col[j] * 32 + lane];
        acc.x += v0.x; acc.y += v0.y; acc.z += v0.z; acc.w += v0.w;
    }
    float dv = d_dinv[warp];
    float4 b = ((const float4*)bias)[lane];
    float4 o;
    o.x = fmaxf(fmaf(acc.x, dv, b.x), 0.f);
    o.y = fmaxf(fmaf(acc.y, dv, b.y), 0.f);
    o.z = fmaxf(fmaf(acc.z, dv, b.z), 0.f);
    o.w = fmaxf(fmaf(acc.w, dv, b.w), 0.f);
    ((float4*)d_bufA)[warp * 32 + lane] = o;
}

// ---------------- pooling: block per graph, thread per feature ----------------
__global__ void k_pool() {
    int g = blockIdx.x, t = threadIdx.x;
    int s = d_gptr[g], e = d_gptr[g + 1];
    float mx = 0.f, sm = 0.f;
    for (int n = s; n < e; n++) {
        float v = d_bufA[n * 128 + t];
        mx = fmaxf(mx, v);
        sm += v;
    }
    float c = (float)(e - s);
    d_pool[g * 256 + t] = mx;
    d_pool[g * 256 + 128 + t] = sm / fmaxf(c, 1.f);
}

// ---------------- MLP head ----------------
__global__ void k_mlp1(const float* __restrict__ W, const float* __restrict__ b) {
    __shared__ float a[256];
    int g = blockIdx.x, t = threadIdx.x;
    a[t]       = d_pool[g * 256 + t];
    a[t + 128] = d_pool[g * 256 + 128 + t];
    __syncthreads();
    float acc = b[t];
    #pragma unroll 8
    for (int k = 0; k < 256; k++) acc = fmaf(a[k], W[k * 128 + t], acc);
    d_m1[g * 128 + t] = fmaxf(acc, 0.f);
}

__global__ void k_mlp2(const float* __restrict__ W, const float* __restrict__ b) {
    __shared__ float a[128];
    int g = blockIdx.x, t = threadIdx.x;
    a[t] = d_m1[g * 128 + t];
    __syncthreads();
    float acc = b[t];
    #pragma unroll 8
    for (int k = 0; k < 128; k++) acc = fmaf(a[k], W[k * 128 + t], acc);
    d_m2[g * 128 + t] = fmaxf(acc, 0.f);
}

__global__ void k_out(const float* __restrict__ W3, const float* __restrict__ b3,
                      float* __restrict__ out) {
    int w = (blockIdx.x * blockDim.x + threadIdx.x) >> 5;
    int lane = threadIdx.x & 31;
    if (w >= N_GRAPHS) return;
    float acc = 0.f;
    #pragma unroll
    for (int k = lane; k < 128; k += 32) acc = fmaf(d_m2[w * 128 + k], W3[k], acc);
    #pragma unroll
    for (int o = 16; o; o >>= 1) acc += __shfl_xor_sync(0xFFFFFFFFu, acc, o);
    if (lane == 0) out[w] = 1.f / (1.f + expf(-(acc + b3[0])));
}

// ---------------- launch ----------------
extern "C" void kernel_launch(void* const* d_in, const int* in_sizes, int n_in,
                              void* d_out, int out_size) {
    const float* x   = (const float*)d_in[0];
    const int*   ei  = (const int*)d_in[1];   // int32 or int64 words; detected
    const int*   bat = (const int*)d_in[2];
    const float* W0 = (const float*)d_in[3],  *b0 = (const float*)d_in[4];
    const float* W1 = (const float*)d_in[5],  *b1 = (const float*)d_in[6];
    const float* W2 = (const float*)d_in[7],  *b2 = (const float*)d_in[8];
    const float* Wl1 = (const float*)d_in[9],  *bl1 = (const float*)d_in[10];
    const float* Wl2 = (const float*)d_in[11], *bl2 = (const float*)d_in[12];
    const float* Wl3 = (const float*)d_in[13], *bl3 = (const float*)d_in[14];
    float* out = (float*)d_out;

    // graph structure (recomputed every call; deterministic work)
    k_detect<<<1, 1>>>(ei);
    k_zero<<<(N_NODES + 255) / 256, 256>>>();
    k_prep<<<(N_EDGES + 255) / 256, 256>>>(ei);
    k_scan<<<1, 1024>>>(0);
    k_fill<<<(N_EDGES + 255) / 256, 256>>>();
    k_dinv<<<(N_NODES + 255) / 256, 256>>>();
    k_ghist<<<(N_NODES + 255) / 256, 256>>>(bat);
    k_scan<<<1, 1024>>>(1);

    const int gemm_blocks = (N_NODES + 63) / 64;
    const int agg_blocks  = (N_NODES * 32 + 255) / 256;

    // layer 1
    k_gemm<<<gemm_blocks, 256>>>(x, 1, W0, N_NODES);
    k_agg<<<agg_blocks, 256>>>(b0);
    // layer 2
    k_gemm<<<gemm_blocks, 256>>>(x, 0, W1, N_NODES);
    k_agg<<<agg_blocks, 256>>>(b1);
    // layer 3
    k_gemm<<<gemm_blocks, 256>>>(x, 0, W2, N_NODES);
    k_agg<<<agg_blocks, 256>>>(b2);

    // pooling + MLP
    k_pool<<<N_GRAPHS, 128>>>();
    k_mlp1<<<N_GRAPHS, 128>>>(Wl1, bl1);
    k_mlp2<<<N_GRAPHS, 128>>>(Wl2, bl2);
    k_out<<<(N_GRAPHS * 32 + 255) / 256, 256>>>(Wl3, bl3, out);
}

// round 4
// speedup vs baseline: 1.7000x; 1.7000x over previous
#include <cuda_runtime.h>
#include <cuda_bf16.h>
#include <math.h>
#include <stdint.h>

#define N_NODES 50000
#define N_EDGES 600000
#define N_GRAPHS 1024
#define NB 196   // ceil(N_NODES/256)

// ---------------- scratch (static device globals; no allocation) ----------------
__device__ float d_bufA[N_NODES * 128];
__device__ float d_bufB[N_NODES * 128];
__device__ float d_dinv[N_NODES];
__device__ int   d_cnt[N_NODES];
__device__ int   d_fill[N_NODES];
__device__ int   d_rowptr[N_NODES + 1];
__device__ int   d_srcE[N_EDGES];
__device__ int   d_dstE[N_EDGES];
__device__ int   d_col[N_EDGES];
__device__ int   d_gptr[N_GRAPHS + 1];
__device__ float d_pool[N_GRAPHS * 256];
__device__ float d_m1[N_GRAPHS * 128];
__device__ float d_m2[N_GRAPHS * 128];
__device__ int   d_mode;
__device__ int   d_bsum[NB];
__device__ int   d_boff[NB];
__device__ unsigned short d_WhiT[128 * 128];  // W^T hi (bf16 bits), [n][k]
__device__ unsigned short d_WloT[128 * 128];  // W^T lo

// ---------------- misc small kernels ----------------
__global__ void k_detect(const int* __restrict__ ei) {
    int z = 0;
    #pragma unroll
    for (int i = 1; i < 64; i += 2) z |= ei[i];
    d_mode = (z == 0) ? 1 : 0;
}

__global__ void k_zero() {
    int i = blockIdx.x * blockDim.x + threadIdx.x;
    if (i < N_NODES) { d_cnt[i] = 0; d_fill[i] = 0; }
}

__device__ __forceinline__ int clampi(int v, int hi) {
    return v < 0 ? 0 : (v > hi ? hi : v);
}

__global__ void k_prep(const int* __restrict__ ei) {
    int e = blockIdx.x * blockDim.x + threadIdx.x;
    if (e < N_EDGES) {
        int s, d;
        if (d_mode) { s = ei[2 * e]; d = ei[2 * (N_EDGES + e)]; }
        else        { s = ei[e];     d = ei[N_EDGES + e]; }
        s = clampi(s, N_NODES - 1);
        d = clampi(d, N_NODES - 1);
        d_srcE[e] = s;
        d_dstE[e] = d;
        atomicAdd(&d_cnt[d], 1);
    }
}

// per-block sums of cnt (+ dinv)
__global__ void k_bsum() {
    __shared__ int wsum[8];
    int tid = threadIdx.x, lane = tid & 31, w = tid >> 5;
    int i = blockIdx.x * 256 + tid;
    int v = (i < N_NODES) ? d_cnt[i] : 0;
    if (i < N_NODES) d_dinv[i] = rsqrtf((float)v + 1.0f);
    int s = v;
    #pragma unroll
    for (int o = 16; o; o >>= 1) s += __shfl_xor_sync(0xFFFFFFFFu, s, o);
    if (lane == 0) wsum[w] = s;
    __syncthreads();
    if (tid == 0) {
        int t = 0;
        #pragma unroll
        for (int j = 0; j < 8; j++) t += wsum[j];
        d_bsum[blockIdx.x] = t;
    }
}

// scan NB block sums (1 block, 256 threads)
__global__ void k_boff() {
    __shared__ int wsum[9];
    int tid = threadIdx.x, lane = tid & 31, w = tid >> 5;
    int v = (tid < NB) ? d_bsum[tid] : 0;
    int incl = v;
    #pragma unroll
    for (int o = 1; o < 32; o <<= 1) {
        int t = __shfl_up_sync(0xFFFFFFFFu, incl, o);
        if (lane >= o) incl += t;
    }
    if (lane == 31) wsum[w] = incl;
    __syncthreads();
    if (tid == 0) {
        int run = 0;
        #pragma unroll
        for (int j = 0; j < 8; j++) { int t = wsum[j]; wsum[j] = run; run += t; }
        wsum[8] = run;
    }
    __syncthreads();
    int excl = wsum[w] + incl - v;
    if (tid < NB) d_boff[tid] = excl;
    if (tid == 0) d_rowptr[N_NODES] = wsum[8];
}

// local exclusive scan + block offset -> rowptr
__global__ void k_sfin() {
    __shared__ int wsum[8];
    int tid = threadIdx.x, lane = tid & 31, w = tid >> 5;
    int i = blockIdx.x * 256 + tid;
    int v = (i < N_NODES) ? d_cnt[i] : 0;
    int incl = v;
    #pragma unroll
    for (int o = 1; o < 32; o <<= 1) {
        int t = __shfl_up_sync(0xFFFFFFFFu, incl, o);
        if (lane >= o) incl += t;
    }
    if (lane == 31) wsum[w] = incl;
    __syncthreads();
    if (tid == 0) {
        int run = 0;
        #pragma unroll
        for (int j = 0; j < 8; j++) { int t = wsum[j]; wsum[j] = run; run += t; }
    }
    __syncthreads();
    if (i < N_NODES) d_rowptr[i] = d_boff[blockIdx.x] + wsum[w] + incl - v;
}

__global__ void k_fill() {
    int e = blockIdx.x * blockDim.x + threadIdx.x;
    if (e < N_EDGES) {
        int d = d_dstE[e];
        int pos = d_rowptr[d] + atomicAdd(&d_fill[d], 1);
        d_col[pos] = d_srcE[e];
    }
}

// gptr via binary search on sorted batch_index
__global__ void k_gptr(const int* __restrict__ batch) {
    int g = blockIdx.x * blockDim.x + threadIdx.x;
    if (g > N_GRAPHS) return;
    int lo = 0, hi = N_NODES;
    while (lo < hi) {
        int mid = (lo + hi) >> 1;
        int b = d_mode ? batch[2 * mid] : batch[mid];
        if (b < g) lo = mid + 1; else hi = mid;
    }
    d_gptr[g] = lo;
}

// ---------------- W pre-split: W^T hi/lo bf16, [n][k] ----------------
__global__ void k_wprep(const float* __restrict__ W) {
    int idx = blockIdx.x * blockDim.x + threadIdx.x;
    if (idx >= 128 * 128) return;
    int n = idx >> 7, k = idx & 127;
    float w = W[k * 128 + n];
    __nv_bfloat16 h = __float2bfloat16(w);
    float r = w - __bfloat162float(h);
    __nv_bfloat16 l = __float2bfloat16(r);
    d_WhiT[n * 128 + k] = __bfloat16_as_ushort(h);
    d_WloT[n * 128 + k] = __bfloat16_as_ushort(l);
}

// ---------------- bf16-split tensor-core GEMM via mma.sync ----------------
// d_bufB = (X @ W) * dinv[row];  128x128 block tile, K=128
// smem layout: 4 tiles (Ah, Al, Bh, Bl), each 128 rows x 136 halves (68 words).
// 68 mod 32 = 4  =>  all fragment LDS.32 loads are bank-conflict-free.
#define SROW 68                      // words per row
#define TILE_W (128 * SROW)          // words per tile
#define GEMM_SMEM (4 * TILE_W * 4)   // bytes

__device__ __forceinline__ void mma16816(float* d, uint32_t a0, uint32_t a1,
                                         uint32_t a2, uint32_t a3,
                                         uint32_t b0, uint32_t b1) {
    asm volatile(
        "mma.sync.aligned.m16n8k16.row.col.f32.bf16.bf16.f32 "
        "{%0,%1,%2,%3}, {%4,%5,%6,%7}, {%8,%9}, {%0,%1,%2,%3};"
        : "+f"(d[0]), "+f"(d[1]), "+f"(d[2]), "+f"(d[3])
        : "r"(a0), "r"(a1), "r"(a2), "r"(a3), "r"(b0), "r"(b1));
}

__device__ __forceinline__ void split2(float a, float b, uint32_t& hi, uint32_t& lo) {
    __nv_bfloat16 ha = __float2bfloat16(a), hb = __float2bfloat16(b);
    float ra = a - __bfloat162float(ha), rb = b - __bfloat162float(hb);
    __nv_bfloat16 la = __float2bfloat16(ra), lb = __float2bfloat16(rb);
    hi = ((uint32_t)__bfloat16_as_ushort(hb) << 16) | (uint32_t)__bfloat16_as_ushort(ha);
    lo = ((uint32_t)__bfloat16_as_ushort(lb) << 16) | (uint32_t)__bfloat16_as_ushort(la);
}

__global__ void __launch_bounds__(256) k_gemm_mma(const float* __restrict__ Xext,
                                                  int useExt, int M) {
    extern __shared__ uint32_t sm[];                 // word-addressed
    uint32_t* AH = sm;
    uint32_t* AL = sm + TILE_W;
    uint32_t* BH = sm + 2 * TILE_W;
    uint32_t* BL = sm + 3 * TILE_W;
    const float* __restrict__ X = useExt ? Xext : d_bufA;

    int tid = threadIdx.x;
    int row0 = blockIdx.x * 128;

    // stage B (pre-split W^T, coalesced u32 loads)
    #pragma unroll
    for (int it = 0; it < 32; it++) {
        int idx = tid + it * 256;                    // 0 .. 8191
        int n = idx >> 6, kw = idx & 63;
        BH[n * SROW + kw] = ((const uint32_t*)d_WhiT)[idx];
        BL[n * SROW + kw] = ((const uint32_t*)d_WloT)[idx];
    }
    // stage A (fp32 -> hi/lo bf16 split)
    #pragma unroll
    for (int it = 0; it < 32; it++) {
        int idx = tid + it * 256;
        int r = idx >> 6, kw = idx & 63;
        float2 v = (row0 + r < M) ? ((const float2*)X)[(size_t)(row0 + r) * 64 + kw]
                                  : make_float2(0.f, 0.f);
        uint32_t hi, lo;
        split2(v.x, v.y, hi, lo);
        AH[r * SROW + kw] = hi;
        AL[r * SROW + kw] = lo;
    }
    __syncthreads();

    int wid = tid >> 5, lane = tid & 31;
    int g = lane >> 2, tg = lane & 3;                // group / thread-in-group
    int mb = (wid >> 1) * 32;                        // warp M base (4 warps)
    int nb = (wid & 1) * 64;                         // warp N base (2 warps)

    float acc[2][8][4];
    #pragma unroll
    for (int mt = 0; mt < 2; mt++)
        #pragma unroll
        for (int nt = 0; nt < 8; nt++)
            #pragma unroll
            for (int q = 0; q < 4; q++) acc[mt][nt][q] = 0.f;

    #pragma unroll
    for (int ks = 0; ks < 8; ks++) {
        int kw = ks * 8;
        uint32_t ah[2][4], al[2][4];
        #pragma unroll
        for (int mt = 0; mt < 2; mt++) {
            int r0 = (mb + mt * 16 + g) * SROW, r1 = (mb + mt * 16 + 8 + g) * SROW;
            ah[mt][0] = AH[r0 + kw + tg];     ah[mt][1] = AH[r1 + kw + tg];
            ah[mt][2] = AH[r0 + kw + 4 + tg]; ah[mt][3] = AH[r1 + kw + 4 + tg];
            al[mt][0] = AL[r0 + kw + tg];     al[mt][1] = AL[r1 + kw + tg];
            al[mt][2] = AL[r0 + kw + 4 + tg]; al[mt][3] = AL[r1 + kw + 4 + tg];
        }
        #pragma unroll
        for (int nt = 0; nt < 8; nt++) {
            int nr = (nb + nt * 8 + g) * SROW;
            uint32_t bh0 = BH[nr + kw + tg], bh1 = BH[nr + kw + 4 + tg];
            uint32_t bl0 = BL[nr + kw + tg], bl1 = BL[nr + kw + 4 + tg];
            #pragma unroll
            for (int mt = 0; mt < 2; mt++) {
                mma16816(acc[mt][nt], ah[mt][0], ah[mt][1], ah[mt][2], ah[mt][3], bh0, bh1);
                mma16816(acc[mt][nt], ah[mt][0], ah[mt][1], ah[mt][2], ah[mt][3], bl0, bl1);
                mma16816(acc[mt][nt], al[mt][0], al[mt][1], al[mt][2], al[mt][3], bh0, bh1);
            }
        }
    }

    // epilogue: scale by dinv[row], store fp32
    #pragma unroll
    for (int mt = 0; mt < 2; mt++) {
        int r0 = row0 + mb + mt * 16 + g;
        int r1 = r0 + 8;
        float dv0 = (r0 < M) ? d_dinv[r0] : 0.f;
        float dv1 = (r1 < M) ? d_dinv[r1] : 0.f;
        #pragma unroll
        for (int nt = 0; nt < 8; nt++) {
            int c = nb + nt * 8 + tg * 2;
            if (r0 < M)
                *(float2*)&d_bufB[(size_t)r0 * 128 + c] =
                    make_float2(acc[mt][nt][0] * dv0, acc[mt][nt][1] * dv0);
            if (r1 < M)
                *(float2*)&d_bufB[(size_t)r1 * 128 + c] =
                    make_float2(acc[mt][nt][2] * dv1, acc[mt][nt][3] * dv1);
        }
    }
}

// ---------------- aggregate: out = relu(dinv[i]*(G[i] + sum_nbr G[src]) + b) ----
__global__ void k_agg(const float* __restrict__ bias) {
    int warp = (blockIdx.x * blockDim.x + threadIdx.x) >> 5;
    int lane = threadIdx.x & 31;
    if (warp >= N_NODES) return;
    const float4* __restrict__ G4 = (const float4*)d_bufB;

    float4 acc = G4[warp * 32 + lane];
    int s = d_rowptr[warp], e = d_rowptr[warp + 1];
    int j = s;
    for (; j + 1 < e; j += 2) {
        int s0 = d_col[j], s1 = d_col[j + 1];
        float4 v0 = G4[s0 * 32 + lane];
        float4 v1 = G4[s1 * 32 + lane];
        acc.x += v0.x + v1.x; acc.y += v0.y + v1.y;
        acc.z += v0.z + v1.z; acc.w += v0.w + v1.w;
    }
    if (j < e) {
        float4 v0 = G4[d_col[j] * 32 + lane];
        acc.x += v0.x; acc.y += v0.y; acc.z += v0.z; acc.w += v0.w;
    }
    float dv = d_dinv[warp];
    float4 b = ((const float4*)bias)[lane];
    float4 o;
    o.x = fmaxf(fmaf(acc.x, dv, b.x), 0.f);
    o.y = fmaxf(fmaf(acc.y, dv, b.y), 0.f);
    o.z = fmaxf(fmaf(acc.z, dv, b.z), 0.f);
    o.w = fmaxf(fmaf(acc.w, dv, b.w), 0.f);
    ((float4*)d_bufA)[warp * 32 + lane] = o;
}

// ---------------- pooling + MLP head ----------------
__global__ void k_pool() {
    int g = blockIdx.x, t = threadIdx.x;
    int s = d_gptr[g], e = d_gptr[g + 1];
    float mx = 0.f, sm = 0.f;
    for (int n = s; n < e; n++) {
        float v = d_bufA[n * 128 + t];
        mx = fmaxf(mx, v);
        sm += v;
    }
    float c = (float)(e - s);
    d_pool[g * 256 + t] = mx;
    d_pool[g * 256 + 128 + t] = sm / fmaxf(c, 1.f);
}

__global__ void k_mlp1(const float* __restrict__ W, const float* __restrict__ b) {
    __shared__ float a[256];
    int g = blockIdx.x, t = threadIdx.x;
    a[t]       = d_pool[g * 256 + t];
    a[t + 128] = d_pool[g * 256 + 128 + t];
    __syncthreads();
    float acc = b[t];
    #pragma unroll 8
    for (int k = 0; k < 256; k++) acc = fmaf(a[k], W[k * 128 + t], acc);
    d_m1[g * 128 + t] = fmaxf(acc, 0.f);
}

__global__ void k_mlp2(const float* __restrict__ W, const float* __restrict__ b) {
    __shared__ float a[128];
    int g = blockIdx.x, t = threadIdx.x;
    a[t] = d_m1[g * 128 + t];
    __syncthreads();
    float acc = b[t];
    #pragma unroll 8
    for (int k = 0; k < 128; k++) acc = fmaf(a[k], W[k * 128 + t], acc);
    d_m2[g * 128 + t] = fmaxf(acc, 0.f);
}

__global__ void k_out(const float* __restrict__ W3, const float* __restrict__ b3,
                      float* __restrict__ out) {
    int w = (blockIdx.x * blockDim.x + threadIdx.x) >> 5;
    int lane = threadIdx.x & 31;
    if (w >= N_GRAPHS) return;
    float acc = 0.f;
    #pragma unroll
    for (int k = lane; k < 128; k += 32) acc = fmaf(d_m2[w * 128 + k], W3[k], acc);
    #pragma unroll
    for (int o = 16; o; o >>= 1) acc += __shfl_xor_sync(0xFFFFFFFFu, acc, o);
    if (lane == 0) out[w] = 1.f / (1.f + expf(-(acc + b3[0])));
}

// ---------------- launch ----------------
extern "C" void kernel_launch(void* const* d_in, const int* in_sizes, int n_in,
                              void* d_out, int out_size) {
    const float* x   = (const float*)d_in[0];
    const int*   ei  = (const int*)d_in[1];
    const int*   bat = (const int*)d_in[2];
    const float* W0 = (const float*)d_in[3],  *b0 = (const float*)d_in[4];
    const float* W1 = (const float*)d_in[5],  *b1 = (const float*)d_in[6];
    const float* W2 = (const float*)d_in[7],  *b2 = (const float*)d_in[8];
    const float* Wl1 = (const float*)d_in[9],  *bl1 = (const float*)d_in[10];
    const float* Wl2 = (const float*)d_in[11], *bl2 = (const float*)d_in[12];
    const float* Wl3 = (const float*)d_in[13], *bl3 = (const float*)d_in[14];
    float* out = (float*)d_out;

    static int smem_set = 0;
    if (!smem_set) {
        cudaFuncSetAttribute(k_gemm_mma, cudaFuncAttributeMaxDynamicSharedMemorySize,
                             GEMM_SMEM);
        smem_set = 1;
    }

    // graph structure
    k_detect<<<1, 1>>>(ei);
    k_zero<<<NB, 256>>>();
    k_prep<<<(N_EDGES + 255) / 256, 256>>>(ei);
    k_bsum<<<NB, 256>>>();
    k_boff<<<1, 256>>>();
    k_sfin<<<NB, 256>>>();
    k_fill<<<(N_EDGES + 255) / 256, 256>>>();
    k_gptr<<<5, 256>>>(bat);

    const int gemm_blocks  = (N_NODES + 127) / 128;
    const int agg_blocks   = (N_NODES * 32 + 255) / 256;
    const int wprep_blocks = (128 * 128 + 255) / 256;

    k_wprep<<<wprep_blocks, 256>>>(W0);
    k_gemm_mma<<<gemm_blocks, 256, GEMM_SMEM>>>(x, 1, N_NODES);
    k_agg<<<agg_blocks, 256>>>(b0);

    k_wprep<<<wprep_blocks, 256>>>(W1);
    k_gemm_mma<<<gemm_blocks, 256, GEMM_SMEM>>>(x, 0, N_NODES);
    k_agg<<<agg_blocks, 256>>>(b1);

    k_wprep<<<wprep_blocks, 256>>>(W2);
    k_gemm_mma<<<gemm_blocks, 256, GEMM_SMEM>>>(x, 0, N_NODES);
    k_agg<<<agg_blocks, 256>>>(b2);

    k_pool<<<N_GRAPHS, 128>>>();
    k_mlp1<<<N_GRAPHS, 128>>>(Wl1, bl1);
    k_mlp2<<<N_GRAPHS, 128>>>(Wl2, bl2);
    k_out<<<(N_GRAPHS * 32 + 255) / 256, 256>>>(Wl3, bl3, out);
}

// round 5
// speedup vs baseline: 2.0099x; 1.1823x over previous
#include <cuda_runtime.h>
#include <cuda_bf16.h>
#include <cuda_fp16.h>
#include <math.h>
#include <stdint.h>

#define N_NODES 50000
#define N_EDGES 600000
#define N_GRAPHS 1024
#define NB 196   // ceil(N_NODES/256)

// ---------------- scratch (static device globals; no allocation) ----------------
__device__ __half d_bufAh[N_NODES * 128];   // aggregated layer output (fp16)
__device__ __half d_bufBh[N_NODES * 128];   // G = (X@W)*dinv (fp16)
__device__ float  d_dinv[N_NODES];
__device__ int    d_cnt[N_NODES];
__device__ int    d_fill[N_NODES];
__device__ int    d_rowptr[N_NODES + 1];
__device__ int    d_srcE[N_EDGES];
__device__ int    d_dstE[N_EDGES];
__device__ int    d_col[N_EDGES];
__device__ int    d_gptr[N_GRAPHS + 1];
__device__ float  d_pool[N_GRAPHS * 256];
__device__ float  d_m1[N_GRAPHS * 128];
__device__ float  d_m2[N_GRAPHS * 128];
__device__ int    d_mode;
__device__ int    d_bsum[NB];
__device__ int    d_boff[NB];
__device__ unsigned short d_WhiT[3][128 * 128];  // W^T hi (bf16 bits), [n][k]
__device__ unsigned short d_WloT[3][128 * 128];  // W^T lo

// ---------------- misc small kernels ----------------
__global__ void k_zero(const int* __restrict__ ei) {
    int i = blockIdx.x * blockDim.x + threadIdx.x;
    if (i < N_NODES) { d_cnt[i] = 0; d_fill[i] = 0; }
    if (blockIdx.x == 0 && threadIdx.x == 0) {
        int z = 0;
        #pragma unroll
        for (int j = 1; j < 64; j += 2) z |= ei[j];
        d_mode = (z == 0) ? 1 : 0;
    }
}

__device__ __forceinline__ int clampi(int v, int hi) {
    return v < 0 ? 0 : (v > hi ? hi : v);
}

__global__ void k_prep(const int* __restrict__ ei) {
    int e = blockIdx.x * blockDim.x + threadIdx.x;
    if (e < N_EDGES) {
        int s, d;
        if (d_mode) { s = ei[2 * e]; d = ei[2 * (N_EDGES + e)]; }
        else        { s = ei[e];     d = ei[N_EDGES + e]; }
        s = clampi(s, N_NODES - 1);
        d = clampi(d, N_NODES - 1);
        d_srcE[e] = s;
        d_dstE[e] = d;
        atomicAdd(&d_cnt[d], 1);
    }
}

// per-block sums of cnt (+ dinv)
__global__ void k_bsum() {
    __shared__ int wsum[8];
    int tid = threadIdx.x, lane = tid & 31, w = tid >> 5;
    int i = blockIdx.x * 256 + tid;
    int v = (i < N_NODES) ? d_cnt[i] : 0;
    if (i < N_NODES) d_dinv[i] = rsqrtf((float)v + 1.0f);
    int s = v;
    #pragma unroll
    for (int o = 16; o; o >>= 1) s += __shfl_xor_sync(0xFFFFFFFFu, s, o);
    if (lane == 0) wsum[w] = s;
    __syncthreads();
    if (tid == 0) {
        int t = 0;
        #pragma unroll
        for (int j = 0; j < 8; j++) t += wsum[j];
        d_bsum[blockIdx.x] = t;
    }
}

// scan NB block sums (1 block, 256 threads)
__global__ void k_boff() {
    __shared__ int wsum[9];
    int tid = threadIdx.x, lane = tid & 31, w = tid >> 5;
    int v = (tid < NB) ? d_bsum[tid] : 0;
    int incl = v;
    #pragma unroll
    for (int o = 1; o < 32; o <<= 1) {
        int t = __shfl_up_sync(0xFFFFFFFFu, incl, o);
        if (lane >= o) incl += t;
    }
    if (lane == 31) wsum[w] = incl;
    __syncthreads();
    if (tid == 0) {
        int run = 0;
        #pragma unroll
        for (int j = 0; j < 8; j++) { int t = wsum[j]; wsum[j] = run; run += t; }
        wsum[8] = run;
    }
    __syncthreads();
    int excl = wsum[w] + incl - v;
    if (tid < NB) d_boff[tid] = excl;
    if (tid == 0) d_rowptr[N_NODES] = wsum[8];
}

// local exclusive scan + block offset -> rowptr
__global__ void k_sfin() {
    __shared__ int wsum[8];
    int tid = threadIdx.x, lane = tid & 31, w = tid >> 5;
    int i = blockIdx.x * 256 + tid;
    int v = (i < N_NODES) ? d_cnt[i] : 0;
    int incl = v;
    #pragma unroll
    for (int o = 1; o < 32; o <<= 1) {
        int t = __shfl_up_sync(0xFFFFFFFFu, incl, o);
        if (lane >= o) incl += t;
    }
    if (lane == 31) wsum[w] = incl;
    __syncthreads();
    if (tid == 0) {
        int run = 0;
        #pragma unroll
        for (int j = 0; j < 8; j++) { int t = wsum[j]; wsum[j] = run; run += t; }
    }
    __syncthreads();
    if (i < N_NODES) d_rowptr[i] = d_boff[blockIdx.x] + wsum[w] + incl - v;
}

__global__ void k_fill() {
    int e = blockIdx.x * blockDim.x + threadIdx.x;
    if (e < N_EDGES) {
        int d = d_dstE[e];
        int pos = d_rowptr[d] + atomicAdd(&d_fill[d], 1);
        d_col[pos] = d_srcE[e];
    }
}

// gptr via binary search on sorted batch_index
__global__ void k_gptr(const int* __restrict__ batch) {
    int g = blockIdx.x * blockDim.x + threadIdx.x;
    if (g > N_GRAPHS) return;
    int lo = 0, hi = N_NODES;
    while (lo < hi) {
        int mid = (lo + hi) >> 1;
        int b = d_mode ? batch[2 * mid] : batch[mid];
        if (b < g) lo = mid + 1; else hi = mid;
    }
    d_gptr[g] = lo;
}

// ---------------- W pre-split (all 3 layers): W^T hi/lo bf16, [n][k] ------------
__global__ void k_wprep3(const float* __restrict__ W0, const float* __restrict__ W1,
                         const float* __restrict__ W2) {
    int idx = blockIdx.x * blockDim.x + threadIdx.x;
    if (idx >= 3 * 128 * 128) return;
    int which = idx >> 14, id = idx & 16383;
    const float* W = (which == 0) ? W0 : (which == 1) ? W1 : W2;
    int n = id >> 7, k = id & 127;
    float w = W[k * 128 + n];
    __nv_bfloat16 h = __float2bfloat16(w);
    float r = w - __bfloat162float(h);
    __nv_bfloat16 l = __float2bfloat16(r);
    d_WhiT[which][n * 128 + k] = __bfloat16_as_ushort(h);
    d_WloT[which][n * 128 + k] = __bfloat16_as_ushort(l);
}

// ---------------- bf16-split tensor-core GEMM via mma.sync ----------------
// d_bufBh = fp16( (X @ W) * dinv[row] );  128x128 block tile, K=128
#define SROW 68                      // words per row (68 mod 32 = 4: conflict-free)
#define TILE_W (128 * SROW)
#define GEMM_SMEM (4 * TILE_W * 4)

__device__ __forceinline__ void mma16816(float* d, uint32_t a0, uint32_t a1,
                                         uint32_t a2, uint32_t a3,
                                         uint32_t b0, uint32_t b1) {
    asm volatile(
        "mma.sync.aligned.m16n8k16.row.col.f32.bf16.bf16.f32 "
        "{%0,%1,%2,%3}, {%4,%5,%6,%7}, {%8,%9}, {%0,%1,%2,%3};"
        : "+f"(d[0]), "+f"(d[1]), "+f"(d[2]), "+f"(d[3])
        : "r"(a0), "r"(a1), "r"(a2), "r"(a3), "r"(b0), "r"(b1));
}

__device__ __forceinline__ void splitf2(float a, float b, uint32_t& hi, uint32_t& lo) {
    __nv_bfloat16 ha = __float2bfloat16(a), hb = __float2bfloat16(b);
    float ra = a - __bfloat162float(ha), rb = b - __bfloat162float(hb);
    __nv_bfloat16 la = __float2bfloat16(ra), lb = __float2bfloat16(rb);
    hi = ((uint32_t)__bfloat16_as_ushort(hb) << 16) | (uint32_t)__bfloat16_as_ushort(ha);
    lo = ((uint32_t)__bfloat16_as_ushort(lb) << 16) | (uint32_t)__bfloat16_as_ushort(la);
}

__global__ void __launch_bounds__(256) k_gemm_mma(const float* __restrict__ Xext,
                                                  int useExt, int widx, int M) {
    extern __shared__ uint32_t sm[];
    uint32_t* AH = sm;
    uint32_t* AL = sm + TILE_W;
    uint32_t* BH = sm + 2 * TILE_W;
    uint32_t* BL = sm + 3 * TILE_W;

    int tid = threadIdx.x;
    int row0 = blockIdx.x * 128;

    // stage B (pre-split W^T, coalesced u32 loads)
    const uint32_t* WH = (const uint32_t*)d_WhiT[widx];
    const uint32_t* WL = (const uint32_t*)d_WloT[widx];
    #pragma unroll
    for (int it = 0; it < 32; it++) {
        int idx = tid + it * 256;
        int n = idx >> 6, kw = idx & 63;
        BH[n * SROW + kw] = WH[idx];
        BL[n * SROW + kw] = WL[idx];
    }
    // stage A (fp32 or fp16 input -> hi/lo bf16 split)
    if (useExt) {
        #pragma unroll
        for (int it = 0; it < 32; it++) {
            int idx = tid + it * 256;
            int r = idx >> 6, kw = idx & 63;
            float2 v = (row0 + r < M) ? ((const float2*)Xext)[(size_t)(row0 + r) * 64 + kw]
                                      : make_float2(0.f, 0.f);
            uint32_t hi, lo;
            splitf2(v.x, v.y, hi, lo);
            AH[r * SROW + kw] = hi;
            AL[r * SROW + kw] = lo;
        }
    } else {
        const uint32_t* Xh = (const uint32_t*)d_bufAh;
        #pragma unroll
        for (int it = 0; it < 32; it++) {
            int idx = tid + it * 256;
            int r = idx >> 6, kw = idx & 63;
            uint32_t p = (row0 + r < M) ? Xh[(size_t)(row0 + r) * 64 + kw] : 0u;
            __half2 h2 = *(__half2*)&p;
            float2 v = __half22float2(h2);
            uint32_t hi, lo;
            splitf2(v.x, v.y, hi, lo);
            AH[r * SROW + kw] = hi;
            AL[r * SROW + kw] = lo;
        }
    }
    __syncthreads();

    int wid = tid >> 5, lane = tid & 31;
    int g = lane >> 2, tg = lane & 3;
    int mb = (wid >> 1) * 32;
    int nb = (wid & 1) * 64;

    float acc[2][8][4];
    #pragma unroll
    for (int mt = 0; mt < 2; mt++)
        #pragma unroll
        for (int nt = 0; nt < 8; nt++)
            #pragma unroll
            for (int q = 0; q < 4; q++) acc[mt][nt][q] = 0.f;

    #pragma unroll
    for (int ks = 0; ks < 8; ks++) {
        int kw = ks * 8;
        uint32_t ah[2][4], al[2][4];
        #pragma unroll
        for (int mt = 0; mt < 2; mt++) {
            int r0 = (mb + mt * 16 + g) * SROW, r1 = (mb + mt * 16 + 8 + g) * SROW;
            ah[mt][0] = AH[r0 + kw + tg];     ah[mt][1] = AH[r1 + kw + tg];
            ah[mt][2] = AH[r0 + kw + 4 + tg]; ah[mt][3] = AH[r1 + kw + 4 + tg];
            al[mt][0] = AL[r0 + kw + tg];     al[mt][1] = AL[r1 + kw + tg];
            al[mt][2] = AL[r0 + kw + 4 + tg]; al[mt][3] = AL[r1 + kw + 4 + tg];
        }
        #pragma unroll
        for (int nt = 0; nt < 8; nt++) {
            int nr = (nb + nt * 8 + g) * SROW;
            uint32_t bh0 = BH[nr + kw + tg], bh1 = BH[nr + kw + 4 + tg];
            uint32_t bl0 = BL[nr + kw + tg], bl1 = BL[nr + kw + 4 + tg];
            #pragma unroll
            for (int mt = 0; mt < 2; mt++) {
                mma16816(acc[mt][nt], ah[mt][0], ah[mt][1], ah[mt][2], ah[mt][3], bh0, bh1);
                mma16816(acc[mt][nt], ah[mt][0], ah[mt][1], ah[mt][2], ah[mt][3], bl0, bl1);
                mma16816(acc[mt][nt], al[mt][0], al[mt][1], al[mt][2], al[mt][3], bh0, bh1);
            }
        }
    }

    // epilogue: scale by dinv[row], store fp16
    uint32_t* Gout = (uint32_t*)d_bufBh;
    #pragma unroll
    for (int mt = 0; mt < 2; mt++) {
        int r0 = row0 + mb + mt * 16 + g;
        int r1 = r0 + 8;
        float dv0 = (r0 < M) ? d_dinv[r0] : 0.f;
        float dv1 = (r1 < M) ? d_dinv[r1] : 0.f;
        #pragma unroll
        for (int nt = 0; nt < 8; nt++) {
            int c = nb + nt * 8 + tg * 2;
            if (r0 < M) {
                __half2 p = __floats2half2_rn(acc[mt][nt][0] * dv0, acc[mt][nt][1] * dv0);
                Gout[(size_t)r0 * 64 + (c >> 1)] = *(uint32_t*)&p;
            }
            if (r1 < M) {
                __half2 p = __floats2half2_rn(acc[mt][nt][2] * dv1, acc[mt][nt][3] * dv1);
                Gout[(size_t)r1 * 64 + (c >> 1)] = *(uint32_t*)&p;
            }
        }
    }
}

// ---------------- aggregate: outh = fp16(relu(dinv[i]*(G[i]+sum G[src]) + b)) ---
__device__ __forceinline__ float4 h4f(uint2 u) {
    float2 a = __half22float2(*(__half2*)&u.x);
    float2 b = __half22float2(*(__half2*)&u.y);
    return make_float4(a.x, a.y, b.x, b.y);
}

__global__ void k_agg(const float* __restrict__ bias) {
    int warp = (blockIdx.x * blockDim.x + threadIdx.x) >> 5;
    int lane = threadIdx.x & 31;
    if (warp >= N_NODES) return;
    const uint2* __restrict__ G = (const uint2*)d_bufBh;  // 4 halves per lane

    float4 acc = h4f(G[(size_t)warp * 32 + lane]);        // self loop
    int s = d_rowptr[warp], e = d_rowptr[warp + 1];
    int j = s;
    for (; j + 1 < e; j += 2) {
        int s0 = d_col[j], s1 = d_col[j + 1];
        float4 v0 = h4f(G[(size_t)s0 * 32 + lane]);
        float4 v1 = h4f(G[(size_t)s1 * 32 + lane]);
        acc.x += v0.x + v1.x; acc.y += v0.y + v1.y;
        acc.z += v0.z + v1.z; acc.w += v0.w + v1.w;
    }
    if (j < e) {
        float4 v0 = h4f(G[(size_t)d_col[j] * 32 + lane]);
        acc.x += v0.x; acc.y += v0.y; acc.z += v0.z; acc.w += v0.w;
    }
    float dv = d_dinv[warp];
    float4 b = ((const float4*)bias)[lane];
    float ox = fmaxf(fmaf(acc.x, dv, b.x), 0.f);
    float oy = fmaxf(fmaf(acc.y, dv, b.y), 0.f);
    float oz = fmaxf(fmaf(acc.z, dv, b.z), 0.f);
    float ow = fmaxf(fmaf(acc.w, dv, b.w), 0.f);
    __half2 p0 = __floats2half2_rn(ox, oy);
    __half2 p1 = __floats2half2_rn(oz, ow);
    uint2 w;
    w.x = *(uint32_t*)&p0;
    w.y = *(uint32_t*)&p1;
    ((uint2*)d_bufAh)[(size_t)warp * 32 + lane] = w;
}

// ---------------- pooling: block per graph, thread per feature ----------------
__global__ void k_pool() {
    int g = blockIdx.x, t = threadIdx.x;
    int s = d_gptr[g], e = d_gptr[g + 1];
    float mx = 0.f, sm = 0.f;
    for (int n = s; n < e; n++) {
        float v = __half2float(d_bufAh[(size_t)n * 128 + t]);
        mx = fmaxf(mx, v);
        sm += v;
    }
    float c = (float)(e - s);
    d_pool[g * 256 + t] = mx;
    d_pool[g * 256 + 128 + t] = sm / fmaxf(c, 1.f);
}

// ---------------- MLP head ----------------
__global__ void k_mlp1(const float* __restrict__ W, const float* __restrict__ b) {
    __shared__ float a[256];
    int g = blockIdx.x, t = threadIdx.x;
    a[t]       = d_pool[g * 256 + t];
    a[t + 128] = d_pool[g * 256 + 128 + t];
    __syncthreads();
    float acc = b[t];
    #pragma unroll 8
    for (int k = 0; k < 256; k++) acc = fmaf(a[k], W[k * 128 + t], acc);
    d_m1[g * 128 + t] = fmaxf(acc, 0.f);
}

__global__ void k_mlp2(const float* __restrict__ W, const float* __restrict__ b) {
    __shared__ float a[128];
    int g = blockIdx.x, t = threadIdx.x;
    a[t] = d_m1[g * 128 + t];
    __syncthreads();
    float acc = b[t];
    #pragma unroll 8
    for (int k = 0; k < 128; k++) acc = fmaf(a[k], W[k * 128 + t], acc);
    d_m2[g * 128 + t] = fmaxf(acc, 0.f);
}

__global__ void k_out(const float* __restrict__ W3, const float* __restrict__ b3,
                      float* __restrict__ out) {
    int w = (blockIdx.x * blockDim.x + threadIdx.x) >> 5;
    int lane = threadIdx.x & 31;
    if (w >= N_GRAPHS) return;
    float acc = 0.f;
    #pragma unroll
    for (int k = lane; k < 128; k += 32) acc = fmaf(d_m2[w * 128 + k], W3[k], acc);
    #pragma unroll
    for (int o = 16; o; o >>= 1) acc += __shfl_xor_sync(0xFFFFFFFFu, acc, o);
    if (lane == 0) out[w] = 1.f / (1.f + expf(-(acc + b3[0])));
}

// ---------------- launch ----------------
extern "C" void kernel_launch(void* const* d_in, const int* in_sizes, int n_in,
                              void* d_out, int out_size) {
    const float* x   = (const float*)d_in[0];
    const int*   ei  = (const int*)d_in[1];
    const int*   bat = (const int*)d_in[2];
    const float* W0 = (const float*)d_in[3],  *b0 = (const float*)d_in[4];
    const float* W1 = (const float*)d_in[5],  *b1 = (const float*)d_in[6];
    const float* W2 = (const float*)d_in[7],  *b2 = (const float*)d_in[8];
    const float* Wl1 = (const float*)d_in[9],  *bl1 = (const float*)d_in[10];
    const float* Wl2 = (const float*)d_in[11], *bl2 = (const float*)d_in[12];
    const float* Wl3 = (const float*)d_in[13], *bl3 = (const float*)d_in[14];
    float* out = (float*)d_out;

    static int smem_set = 0;
    if (!smem_set) {
        cudaFuncSetAttribute(k_gemm_mma, cudaFuncAttributeMaxDynamicSharedMemorySize,
                             GEMM_SMEM);
        smem_set = 1;
    }

    // graph structure
    k_zero<<<NB, 256>>>(ei);
    k_prep<<<(N_EDGES + 255) / 256, 256>>>(ei);
    k_bsum<<<NB, 256>>>();
    k_boff<<<1, 256>>>();
    k_sfin<<<NB, 256>>>();
    k_fill<<<(N_EDGES + 255) / 256, 256>>>();
    k_gptr<<<5, 256>>>(bat);
    k_wprep3<<<(3 * 128 * 128 + 255) / 256, 256>>>(W0, W1, W2);

    const int gemm_blocks = (N_NODES + 127) / 128;
    const int agg_blocks  = (N_NODES * 32 + 255) / 256;

    k_gemm_mma<<<gemm_blocks, 256, GEMM_SMEM>>>(x, 1, 0, N_NODES);
    k_agg<<<agg_blocks, 256>>>(b0);

    k_gemm_mma<<<gemm_blocks, 256, GEMM_SMEM>>>(x, 0, 1, N_NODES);
    k_agg<<<agg_blocks, 256>>>(b1);

    k_gemm_mma<<<gemm_blocks, 256, GEMM_SMEM>>>(x, 0, 2, N_NODES);
    k_agg<<<agg_blocks, 256>>>(b2);

    k_pool<<<N_GRAPHS, 128>>>();
    k_mlp1<<<N_GRAPHS, 128>>>(Wl1, bl1);
    k_mlp2<<<N_GRAPHS, 128>>>(Wl2, bl2);
    k_out<<<(N_GRAPHS * 32 + 255) / 256, 256>>>(Wl3, bl3, out);
}

// round 6
// speedup vs baseline: 2.1222x; 1.0559x over previous
#include <cuda_runtime.h>
#include <cuda_bf16.h>
#include <cuda_fp16.h>
#include <math.h>
#include <stdint.h>

#define N_NODES 50000
#define N_EDGES 600000
#define N_GRAPHS 1024
#define NB 196   // ceil(N_NODES/256)

// ---------------- scratch (static device globals; zero-initialized) -------------
__device__ __half d_bufAh[N_NODES * 128];   // aggregated layer output (fp16)
__device__ __half d_bufBh[N_NODES * 128];   // G = (X@W)*dinv (fp16)
__device__ float  d_dinv[N_NODES];
__device__ int    d_cnt[N_NODES];           // dst counts; self-restores to 0 in k_fill
__device__ int    d_rowptr[N_NODES + 1];
__device__ int    d_srcE[N_EDGES];
__device__ int    d_dstE[N_EDGES];
__device__ int    d_col[N_EDGES];
__device__ int    d_gptr[N_GRAPHS + 1];
__device__ int    d_bsum[NB];
__device__ unsigned short d_WhiT[3][128 * 128];  // W^T hi (bf16 bits), [n][k]
__device__ unsigned short d_WloT[3][128 * 128];  // W^T lo

__device__ __forceinline__ int clampi(int v, int hi) {
    return v < 0 ? 0 : (v > hi ? hi : v);
}

// int64-vs-int32 detection from the first 64 words of edge_index (per block).
__device__ __forceinline__ int detect_mode(const int* __restrict__ ei) {
    int z = 0;
    #pragma unroll
    for (int j = 1; j < 64; j += 2) z |= ei[j];
    return (z == 0) ? 1 : 0;
}

// ---------------- edge prep: dtype-adaptive load + dst histogram ----------------
__global__ void k_prep(const int* __restrict__ ei) {
    __shared__ int smode;
    if (threadIdx.x == 0) smode = detect_mode(ei);
    __syncthreads();
    int mode = smode;
    int e = blockIdx.x * blockDim.x + threadIdx.x;
    if (e < N_EDGES) {
        int s, d;
        if (mode) { s = ei[2 * e]; d = ei[2 * (N_EDGES + e)]; }
        else      { s = ei[e];     d = ei[N_EDGES + e]; }
        s = clampi(s, N_NODES - 1);
        d = clampi(d, N_NODES - 1);
        d_srcE[e] = s;
        d_dstE[e] = d;
        atomicAdd(&d_cnt[d], 1);
    }
}

// per-block sums of cnt (+ dinv)
__global__ void k_bsum() {
    __shared__ int wsum[8];
    int tid = threadIdx.x, lane = tid & 31, w = tid >> 5;
    int i = blockIdx.x * 256 + tid;
    int v = (i < N_NODES) ? d_cnt[i] : 0;
    if (i < N_NODES) d_dinv[i] = rsqrtf((float)v + 1.0f);
    int s = v;
    #pragma unroll
    for (int o = 16; o; o >>= 1) s += __shfl_xor_sync(0xFFFFFFFFu, s, o);
    if (lane == 0) wsum[w] = s;
    __syncthreads();
    if (tid == 0) {
        int t = 0;
        #pragma unroll
        for (int j = 0; j < 8; j++) t += wsum[j];
        d_bsum[blockIdx.x] = t;
    }
}

// rowptr: each block computes its own prefix over d_bsum (parallel, no serial kernel)
__global__ void k_sfin() {
    __shared__ int wred[8], wred2[8];
    __shared__ int s_boff, s_total;
    __shared__ int wsum[8];
    int tid = threadIdx.x, lane = tid & 31, w = tid >> 5;
    int b = blockIdx.x;

    // prefix of block sums: sum bsum[j] for j < b ; also full total (block 0 only use)
    int sv = (tid < NB) ? d_bsum[tid] : 0;
    int pv = (tid < b) ? sv : 0;
    int tv = sv;
    #pragma unroll
    for (int o = 16; o; o >>= 1) {
        pv += __shfl_xor_sync(0xFFFFFFFFu, pv, o);
        tv += __shfl_xor_sync(0xFFFFFFFFu, tv, o);
    }
    if (lane == 0) { wred[w] = pv; wred2[w] = tv; }
    __syncthreads();
    if (tid == 0) {
        int p = 0, t = 0;
        #pragma unroll
        for (int j = 0; j < 8; j++) { p += wred[j]; t += wred2[j]; }
        s_boff = p;
        s_total = t;
        if (b == 0) d_rowptr[N_NODES] = t;
    }
    __syncthreads();

    // local exclusive scan of cnt + block offset
    int i = b * 256 + tid;
    int v = (i < N_NODES) ? d_cnt[i] : 0;
    int incl = v;
    #pragma unroll
    for (int o = 1; o < 32; o <<= 1) {
        int t = __shfl_up_sync(0xFFFFFFFFu, incl, o);
        if (lane >= o) incl += t;
    }
    if (lane == 31) wsum[w] = incl;
    __syncthreads();
    if (tid == 0) {
        int run = 0;
        #pragma unroll
        for (int j = 0; j < 8; j++) { int t = wsum[j]; wsum[j] = run; run += t; }
    }
    __syncthreads();
    if (i < N_NODES) d_rowptr[i] = s_boff + wsum[w] + incl - v;
}

// CSR scatter; d_cnt doubles as the cursor and self-restores to 0
__global__ void k_fill() {
    int e = blockIdx.x * blockDim.x + threadIdx.x;
    if (e < N_EDGES) {
        int d = d_dstE[e];
        int pos = d_rowptr[d] + atomicSub(&d_cnt[d], 1) - 1;
        d_col[pos] = d_srcE[e];
    }
}

// ---------------- W pre-split (3 layers) + gptr binary search, fused ------------
__global__ void k_wgp(const float* __restrict__ W0, const float* __restrict__ W1,
                      const float* __restrict__ W2,
                      const int* __restrict__ ei, const int* __restrict__ bat) {
    int b = blockIdx.x;
    if (b < 192) {
        int idx = b * 256 + threadIdx.x;
        int which = idx >> 14, id = idx & 16383;
        const float* W = (which == 0) ? W0 : (which == 1) ? W1 : W2;
        int n = id >> 7, k = id & 127;
        float w = W[k * 128 + n];
        __nv_bfloat16 h = __float2bfloat16(w);
        float r = w - __bfloat162float(h);
        __nv_bfloat16 l = __float2bfloat16(r);
        d_WhiT[which][n * 128 + k] = __bfloat16_as_ushort(h);
        d_WloT[which][n * 128 + k] = __bfloat16_as_ushort(l);
    } else {
        __shared__ int smode;
        if (threadIdx.x == 0) smode = detect_mode(ei);
        __syncthreads();
        int mode = smode;
        int g = (b - 192) * 256 + threadIdx.x;
        if (g > N_GRAPHS) return;
        int lo = 0, hi = N_NODES;
        while (lo < hi) {
            int mid = (lo + hi) >> 1;
            int v = mode ? bat[2 * mid] : bat[mid];
            if (v < g) lo = mid + 1; else hi = mid;
        }
        d_gptr[g] = lo;
    }
}

// ---------------- bf16-split tensor-core GEMM via mma.sync ----------------
// d_bufBh = fp16( (X @ W) * dinv[row] );  128x128 block tile, K=128
#define SROW 68                      // words per row (68 mod 32 = 4: conflict-free)
#define TILE_W (128 * SROW)
#define GEMM_SMEM (4 * TILE_W * 4)

__device__ __forceinline__ void mma16816(float* d, uint32_t a0, uint32_t a1,
                                         uint32_t a2, uint32_t a3,
                                         uint32_t b0, uint32_t b1) {
    asm volatile(
        "mma.sync.aligned.m16n8k16.row.col.f32.bf16.bf16.f32 "
        "{%0,%1,%2,%3}, {%4,%5,%6,%7}, {%8,%9}, {%0,%1,%2,%3};"
        : "+f"(d[0]), "+f"(d[1]), "+f"(d[2]), "+f"(d[3])
        : "r"(a0), "r"(a1), "r"(a2), "r"(a3), "r"(b0), "r"(b1));
}

__device__ __forceinline__ void splitf2(float a, float b, uint32_t& hi, uint32_t& lo) {
    __nv_bfloat16 ha = __float2bfloat16(a), hb = __float2bfloat16(b);
    float ra = a - __bfloat162float(ha), rb = b - __bfloat162float(hb);
    __nv_bfloat16 la = __float2bfloat16(ra), lb = __float2bfloat16(rb);
    hi = ((uint32_t)__bfloat16_as_ushort(hb) << 16) | (uint32_t)__bfloat16_as_ushort(ha);
    lo = ((uint32_t)__bfloat16_as_ushort(lb) << 16) | (uint32_t)__bfloat16_as_ushort(la);
}

__global__ void __launch_bounds__(256) k_gemm_mma(const float* __restrict__ Xext,
                                                  int useExt, int widx, int M) {
    extern __shared__ uint32_t sm[];
    uint32_t* AH = sm;
    uint32_t* AL = sm + TILE_W;
    uint32_t* BH = sm + 2 * TILE_W;
    uint32_t* BL = sm + 3 * TILE_W;

    int tid = threadIdx.x;
    int row0 = blockIdx.x * 128;

    const uint32_t* WH = (const uint32_t*)d_WhiT[widx];
    const uint32_t* WL = (const uint32_t*)d_WloT[widx];
    #pragma unroll
    for (int it = 0; it < 32; it++) {
        int idx = tid + it * 256;
        int n = idx >> 6, kw = idx & 63;
        BH[n * SROW + kw] = WH[idx];
        BL[n * SROW + kw] = WL[idx];
    }
    if (useExt) {
        #pragma unroll
        for (int it = 0; it < 32; it++) {
            int idx = tid + it * 256;
            int r = idx >> 6, kw = idx & 63;
            float2 v = (row0 + r < M) ? ((const float2*)Xext)[(size_t)(row0 + r) * 64 + kw]
                                      : make_float2(0.f, 0.f);
            uint32_t hi, lo;
            splitf2(v.x, v.y, hi, lo);
            AH[r * SROW + kw] = hi;
            AL[r * SROW + kw] = lo;
        }
    } else {
        const uint32_t* Xh = (const uint32_t*)d_bufAh;
        #pragma unroll
        for (int it = 0; it < 32; it++) {
            int idx = tid + it * 256;
            int r = idx >> 6, kw = idx & 63;
            uint32_t p = (row0 + r < M) ? Xh[(size_t)(row0 + r) * 64 + kw] : 0u;
            __half2 h2 = *(__half2*)&p;
            float2 v = __half22float2(h2);
            uint32_t hi, lo;
            splitf2(v.x, v.y, hi, lo);
            AH[r * SROW + kw] = hi;
            AL[r * SROW + kw] = lo;
        }
    }
    __syncthreads();

    int wid = tid >> 5, lane = tid & 31;
    int g = lane >> 2, tg = lane & 3;
    int mb = (wid >> 1) * 32;
    int nb = (wid & 1) * 64;

    float acc[2][8][4];
    #pragma unroll
    for (int mt = 0; mt < 2; mt++)
        #pragma unroll
        for (int nt = 0; nt < 8; nt++)
            #pragma unroll
            for (int q = 0; q < 4; q++) acc[mt][nt][q] = 0.f;

    #pragma unroll
    for (int ks = 0; ks < 8; ks++) {
        int kw = ks * 8;
        uint32_t ah[2][4], al[2][4];
        #pragma unroll
        for (int mt = 0; mt < 2; mt++) {
            int r0 = (mb + mt * 16 + g) * SROW, r1 = (mb + mt * 16 + 8 + g) * SROW;
            ah[mt][0] = AH[r0 + kw + tg];     ah[mt][1] = AH[r1 + kw + tg];
            ah[mt][2] = AH[r0 + kw + 4 + tg]; ah[mt][3] = AH[r1 + kw + 4 + tg];
            al[mt][0] = AL[r0 + kw + tg];     al[mt][1] = AL[r1 + kw + tg];
            al[mt][2] = AL[r0 + kw + 4 + tg]; al[mt][3] = AL[r1 + kw + 4 + tg];
        }
        #pragma unroll
        for (int nt = 0; nt < 8; nt++) {
            int nr = (nb + nt * 8 + g) * SROW;
            uint32_t bh0 = BH[nr + kw + tg], bh1 = BH[nr + kw + 4 + tg];
            uint32_t bl0 = BL[nr + kw + tg], bl1 = BL[nr + kw + 4 + tg];
            #pragma unroll
            for (int mt = 0; mt < 2; mt++) {
                mma16816(acc[mt][nt], ah[mt][0], ah[mt][1], ah[mt][2], ah[mt][3], bh0, bh1);
                mma16816(acc[mt][nt], ah[mt][0], ah[mt][1], ah[mt][2], ah[mt][3], bl0, bl1);
                mma16816(acc[mt][nt], al[mt][0], al[mt][1], al[mt][2], al[mt][3], bh0, bh1);
            }
        }
    }

    uint32_t* Gout = (uint32_t*)d_bufBh;
    #pragma unroll
    for (int mt = 0; mt < 2; mt++) {
        int r0 = row0 + mb + mt * 16 + g;
        int r1 = r0 + 8;
        float dv0 = (r0 < M) ? d_dinv[r0] : 0.f;
        float dv1 = (r1 < M) ? d_dinv[r1] : 0.f;
        #pragma unroll
        for (int nt = 0; nt < 8; nt++) {
            int c = nb + nt * 8 + tg * 2;
            if (r0 < M) {
                __half2 p = __floats2half2_rn(acc[mt][nt][0] * dv0, acc[mt][nt][1] * dv0);
                Gout[(size_t)r0 * 64 + (c >> 1)] = *(uint32_t*)&p;
            }
            if (r1 < M) {
                __half2 p = __floats2half2_rn(acc[mt][nt][2] * dv1, acc[mt][nt][3] * dv1);
                Gout[(size_t)r1 * 64 + (c >> 1)] = *(uint32_t*)&p;
            }
        }
    }
}

// ---------------- aggregate: outh = fp16(relu(dinv[i]*(G[i]+sum G[src]) + b)) ---
__device__ __forceinline__ float4 h4f(uint2 u) {
    float2 a = __half22float2(*(__half2*)&u.x);
    float2 b = __half22float2(*(__half2*)&u.y);
    return make_float4(a.x, a.y, b.x, b.y);
}

__global__ void k_agg(const float* __restrict__ bias) {
    int warp = (blockIdx.x * blockDim.x + threadIdx.x) >> 5;
    int lane = threadIdx.x & 31;
    if (warp >= N_NODES) return;
    const uint2* __restrict__ G = (const uint2*)d_bufBh;

    float4 acc = h4f(G[(size_t)warp * 32 + lane]);        // self loop
    int s = d_rowptr[warp], e = d_rowptr[warp + 1];
    int j = s;
    for (; j + 1 < e; j += 2) {
        int s0 = d_col[j], s1 = d_col[j + 1];
        float4 v0 = h4f(G[(size_t)s0 * 32 + lane]);
        float4 v1 = h4f(G[(size_t)s1 * 32 + lane]);
        acc.x += v0.x + v1.x; acc.y += v0.y + v1.y;
        acc.z += v0.z + v1.z; acc.w += v0.w + v1.w;
    }
    if (j < e) {
        float4 v0 = h4f(G[(size_t)d_col[j] * 32 + lane]);
        acc.x += v0.x; acc.y += v0.y; acc.z += v0.z; acc.w += v0.w;
    }
    float dv = d_dinv[warp];
    float4 b = ((const float4*)bias)[lane];
    float ox = fmaxf(fmaf(acc.x, dv, b.x), 0.f);
    float oy = fmaxf(fmaf(acc.y, dv, b.y), 0.f);
    float oz = fmaxf(fmaf(acc.z, dv, b.z), 0.f);
    float ow = fmaxf(fmaf(acc.w, dv, b.w), 0.f);
    __half2 p0 = __floats2half2_rn(ox, oy);
    __half2 p1 = __floats2half2_rn(oz, ow);
    uint2 w;
    w.x = *(uint32_t*)&p0;
    w.y = *(uint32_t*)&p1;
    ((uint2*)d_bufAh)[(size_t)warp * 32 + lane] = w;
}

// ---------------- fused head: pool + mlp1 + mlp2 + out ----------------
__global__ void k_head(const float* __restrict__ Wl1, const float* __restrict__ bl1,
                       const float* __restrict__ Wl2, const float* __restrict__ bl2,
                       const float* __restrict__ Wl3, const float* __restrict__ bl3,
                       float* __restrict__ out) {
    __shared__ float a[256];
    __shared__ float o1[128];
    __shared__ float o2[128];
    __shared__ float red[4];
    int g = blockIdx.x, t = threadIdx.x;
    int lane = t & 31, w = t >> 5;

    int s = d_gptr[g], e = d_gptr[g + 1];
    float mx = 0.f, sm = 0.f;
    for (int n = s; n < e; n++) {
        float v = __half2float(d_bufAh[(size_t)n * 128 + t]);
        mx = fmaxf(mx, v);
        sm += v;
    }
    a[t] = mx;
    a[t + 128] = sm / fmaxf((float)(e - s), 1.f);
    __syncthreads();

    float acc = bl1[t];
    #pragma unroll 8
    for (int k = 0; k < 256; k++) acc = fmaf(a[k], Wl1[k * 128 + t], acc);
    o1[t] = fmaxf(acc, 0.f);
    __syncthreads();

    acc = bl2[t];
    #pragma unroll 8
    for (int k = 0; k < 128; k++) acc = fmaf(o1[k], Wl2[k * 128 + t], acc);
    o2[t] = fmaxf(acc, 0.f);
    __syncthreads();

    float p = o2[t] * Wl3[t];
    #pragma unroll
    for (int o = 16; o; o >>= 1) p += __shfl_xor_sync(0xFFFFFFFFu, p, o);
    if (lane == 0) red[w] = p;
    __syncthreads();
    if (t == 0) {
        float z = red[0] + red[1] + red[2] + red[3] + bl3[0];
        out[g] = 1.f / (1.f + expf(-z));
    }
}

// ---------------- launch ----------------
extern "C" void kernel_launch(void* const* d_in, const int* in_sizes, int n_in,
                              void* d_out, int out_size) {
    const float* x   = (const float*)d_in[0];
    const int*   ei  = (const int*)d_in[1];
    const int*   bat = (const int*)d_in[2];
    const float* W0 = (const float*)d_in[3],  *b0 = (const float*)d_in[4];
    const float* W1 = (const float*)d_in[5],  *b1 = (const float*)d_in[6];
    const float* W2 = (const float*)d_in[7],  *b2 = (const float*)d_in[8];
    const float* Wl1 = (const float*)d_in[9],  *bl1 = (const float*)d_in[10];
    const float* Wl2 = (const float*)d_in[11], *bl2 = (const float*)d_in[12];
    const float* Wl3 = (const float*)d_in[13], *bl3 = (const float*)d_in[14];
    float* out = (float*)d_out;

    static int smem_set = 0;
    if (!smem_set) {
        cudaFuncSetAttribute(k_gemm_mma, cudaFuncAttributeMaxDynamicSharedMemorySize,
                             GEMM_SMEM);
        smem_set = 1;
    }

    // graph structure (d_cnt starts 0: zero-init globals + self-restore in k_fill)
    k_prep<<<(N_EDGES + 255) / 256, 256>>>(ei);
    k_bsum<<<NB, 256>>>();
    k_sfin<<<NB, 256>>>();
    k_fill<<<(N_EDGES + 255) / 256, 256>>>();
    k_wgp<<<197, 256>>>(W0, W1, W2, ei, bat);

    const int gemm_blocks = (N_NODES + 127) / 128;
    const int agg_blocks  = (N_NODES * 32 + 255) / 256;

    k_gemm_mma<<<gemm_blocks, 256, GEMM_SMEM>>>(x, 1, 0, N_NODES);
    k_agg<<<agg_blocks, 256>>>(b0);

    k_gemm_mma<<<gemm_blocks, 256, GEMM_SMEM>>>(x, 0, 1, N_NODES);
    k_agg<<<agg_blocks, 256>>>(b1);

    k_gemm_mma<<<gemm_blocks, 256, GEMM_SMEM>>>(x, 0, 2, N_NODES);
    k_agg<<<agg_blocks, 256>>>(b2);

    k_head<<<N_GRAPHS, 128>>>(Wl1, bl1, Wl2, bl2, Wl3, bl3, out);
}